// round 1
// baseline (speedup 1.0000x reference)
#include <cuda_runtime.h>

#define G 20000
#define NH 4
#define NE 640000
#define NB 128
#define PDIM 600

// ---------------- scratch (static device globals; no runtime alloc) ----------------
__device__ __align__(16) float g_h[G * 256];       // conv1 per-node features (N,4,64)
__device__ __align__(16) float g_es1[G * 4];
__device__ __align__(16) float g_ed1[G * 4];
__device__ __align__(16) float g_lin1[G * 64];     // xc @ lin1_W + lin1_b
__device__ __align__(16) float g_h1[G * 64];
__device__ __align__(16) float g_h2h[G * 4];
__device__ __align__(16) float g_es2[G * 4];
__device__ __align__(16) float g_ed2[G * 4];
__device__ __align__(16) float g_lin2[G];
__device__ __align__(16) float g_feat[G];
__device__ int g_deg[G];
__device__ int g_off[G + 1];
__device__ int g_cur[G];
__device__ int g_csr[NE];
__device__ __align__(16) float g_pout[NB * 64];
__device__ __align__(16) float g_part1[16 * NB * 1024];  // GEMM1 split-K partials
__device__ __align__(16) float g_hid[NB * 1024];

// ---------------- helpers ----------------
__device__ __forceinline__ float lrelu(float v) { return v > 0.f ? v : 0.2f * v; }
__device__ __forceinline__ float sigmoidf(float v) { return 1.f / (1.f + __expf(-v)); }
__device__ __forceinline__ float wredmax(float v) {
#pragma unroll
    for (int o = 16; o; o >>= 1) v = fmaxf(v, __shfl_xor_sync(0xFFFFFFFFu, v, o));
    return v;
}
__device__ __forceinline__ float wredsum(float v) {
#pragma unroll
    for (int o = 16; o; o >>= 1) v += __shfl_xor_sync(0xFFFFFFFFu, v, o);
    return v;
}

// ---------------- CSR build ----------------
__global__ void k_zero_deg() {
    int i = blockIdx.x * blockDim.x + threadIdx.x;
    if (i < G) g_deg[i] = 0;
}
__global__ void k_hist(const int* __restrict__ ei) {
    int i = blockIdx.x * blockDim.x + threadIdx.x;
    if (i < NE) atomicAdd(&g_deg[ei[NE + i]], 1);
}
__global__ void k_scan() {   // single block, 1024 threads
    __shared__ int s[1024];
    int tid = threadIdx.x;
    int carry = 0;
    for (int base = 0; base < G; base += 1024) {
        int v = (base + tid < G) ? g_deg[base + tid] : 0;
        s[tid] = v;
        __syncthreads();
        for (int d = 1; d < 1024; d <<= 1) {
            int t2 = (tid >= d) ? s[tid - d] : 0;
            __syncthreads();
            s[tid] += t2;
            __syncthreads();
        }
        int incl = s[tid];
        if (base + tid < G) {
            g_off[base + tid + 1] = carry + incl;
            g_cur[base + tid] = carry + incl - v;
        }
        int tot = s[1023];
        __syncthreads();
        carry += tot;
    }
    if (tid == 0) g_off[0] = 0;
}
__global__ void k_scatter(const int* __restrict__ ei) {
    int i = blockIdx.x * blockDim.x + threadIdx.x;
    if (i < NE) {
        int d = ei[NE + i];
        int s = ei[i];
        int p = atomicAdd(&g_cur[d], 1);
        g_csr[p] = s;
    }
}

// ---------------- K1: conv1 features, attn scalars, lin1 ----------------
// grid (512, 2), 128 threads.  blockIdx.y selects head-pair (channels y*128..y*128+127)
__global__ __launch_bounds__(128) void k1(const float* __restrict__ x, const int* __restrict__ pos,
                                          const float* __restrict__ ge, const float* __restrict__ W,
                                          const float* __restrict__ as_, const float* __restrict__ ad_,
                                          const float* __restrict__ linW, const float* __restrict__ linb) {
    __shared__ float sW[65 * 128];
    __shared__ float sES[65 * 2], sED[65 * 2];
    __shared__ float sx[65];
    int t = threadIdx.x;
    int half = blockIdx.y;
    int cbase = half * 128;
    for (int i = t; i < 65 * 128; i += 128) {
        int k = i >> 7, c = i & 127;
        sW[i] = W[k * 256 + cbase + c];
    }
    __syncthreads();
    for (int i = t; i < 65 * 2; i += 128) {
        int k = i >> 1, hh = i & 1;
        int h = half * 2 + hh;
        float s = 0.f, d = 0.f;
        for (int c = 0; c < 64; c++) {
            float w = sW[k * 128 + hh * 64 + c];
            s += w * as_[h * 64 + c];
            d += w * ad_[h * 64 + c];
        }
        sES[i] = s;
        sED[i] = d;
    }
    __syncthreads();
    for (int g = blockIdx.x; g < G; g += gridDim.x) {
        if (t == 0) sx[0] = x[g];
        else if (t < 65) sx[t] = ge[pos[g] * 64 + t - 1];
        __syncthreads();
        float acc = 0.f;
#pragma unroll 13
        for (int k = 0; k < 65; k++) acc += sx[k] * sW[k * 128 + t];
        g_h[g * 256 + cbase + t] = acc;
        if (half == 0 && t < 64) {
            float l = linb[t];
            for (int k = 0; k < 65; k++) l += sx[k] * linW[k * 64 + t];
            g_lin1[g * 64 + t] = l;
        }
        if (t < 2) {
            int h = half * 2 + t;
            float s = 0.f, d = 0.f;
            for (int k = 0; k < 65; k++) {
                s += sx[k] * sES[k * 2 + t];
                d += sx[k] * sED[k * 2 + t];
            }
            g_es1[g * 4 + h] = s;
            g_ed1[g * 4 + h] = d;
        }
        __syncthreads();
    }
}

// ---------------- K3: GAT1 aggregation (one warp per node) ----------------
__global__ __launch_bounds__(256) void k3(const float* __restrict__ conv1_b) {
    int warp = (blockIdx.x * blockDim.x + threadIdx.x) >> 5;
    if (warp >= G) return;
    int lane = threadIdx.x & 31;
    int g = warp;
    int o = g_off[g];
    int deg = g_off[g + 1] - o;
    float4 ed = *(const float4*)&g_ed1[g * 4];

    // pass 1: per-head max over edges + self loop
    float m0 = -1e30f, m1 = -1e30f, m2 = -1e30f, m3 = -1e30f;
    for (int e = lane - 1; e < deg; e += 32) {
        int s = (e < 0) ? g : g_csr[o + e];
        float4 es = *(const float4*)&g_es1[s * 4];
        m0 = fmaxf(m0, lrelu(es.x + ed.x));
        m1 = fmaxf(m1, lrelu(es.y + ed.y));
        m2 = fmaxf(m2, lrelu(es.z + ed.z));
        m3 = fmaxf(m3, lrelu(es.w + ed.w));
    }
    m0 = wredmax(m0); m1 = wredmax(m1); m2 = wredmax(m2); m3 = wredmax(m3);

    // pass 2: edge-serial, lanes over channels (c0 = lane*2, lane*2+1)
    int c0 = lane * 2;
    float2 a0 = {0.f, 0.f}, a1 = {0.f, 0.f}, a2 = {0.f, 0.f}, a3 = {0.f, 0.f};
    float d0 = 0.f, d1 = 0.f, d2 = 0.f, d3 = 0.f;
    for (int e = -1; e < deg; e++) {
        int s = (e < 0) ? g : g_csr[o + e];
        float4 es = *(const float4*)&g_es1[s * 4];
        float x0 = __expf(lrelu(es.x + ed.x) - m0);
        float x1 = __expf(lrelu(es.y + ed.y) - m1);
        float x2 = __expf(lrelu(es.z + ed.z) - m2);
        float x3 = __expf(lrelu(es.w + ed.w) - m3);
        d0 += x0; d1 += x1; d2 += x2; d3 += x3;
        const float* hb = &g_h[s * 256 + c0];
        float2 v0 = *(const float2*)(hb);
        float2 v1 = *(const float2*)(hb + 64);
        float2 v2 = *(const float2*)(hb + 128);
        float2 v3 = *(const float2*)(hb + 192);
        a0.x += x0 * v0.x; a0.y += x0 * v0.y;
        a1.x += x1 * v1.x; a1.y += x1 * v1.y;
        a2.x += x2 * v2.x; a2.y += x2 * v2.y;
        a3.x += x3 * v3.x; a3.y += x3 * v3.y;
    }
    float i0 = 1.f / d0, i1 = 1.f / d1, i2 = 1.f / d2, i3 = 1.f / d3;
    float o0 = 0.25f * (a0.x * i0 + a1.x * i1 + a2.x * i2 + a3.x * i3)
             + conv1_b[c0] + g_lin1[g * 64 + c0];
    float o1 = 0.25f * (a0.y * i0 + a1.y * i1 + a2.y * i2 + a3.y * i3)
             + conv1_b[c0 + 1] + g_lin1[g * 64 + c0 + 1];
    float2 r;
    r.x = sigmoidf(o0);
    r.y = sigmoidf(o1);
    *(float2*)&g_h1[g * 64 + c0] = r;
}

// ---------------- K4: layer-2 per-node projections ----------------
__global__ __launch_bounds__(256) void k4(const float* __restrict__ c2W, const float* __restrict__ c2as,
                                          const float* __restrict__ c2ad, const float* __restrict__ l2W) {
    int warp = (blockIdx.x * blockDim.x + threadIdx.x) >> 5;
    if (warp >= G) return;
    int lane = threadIdx.x & 31;
    int g = warp;
    int c0 = lane * 2;
    float2 hv = *(const float2*)&g_h1[g * 64 + c0];
    float d0 = hv.x * c2W[c0 * 4 + 0] + hv.y * c2W[(c0 + 1) * 4 + 0];
    float d1 = hv.x * c2W[c0 * 4 + 1] + hv.y * c2W[(c0 + 1) * 4 + 1];
    float d2 = hv.x * c2W[c0 * 4 + 2] + hv.y * c2W[(c0 + 1) * 4 + 2];
    float d3 = hv.x * c2W[c0 * 4 + 3] + hv.y * c2W[(c0 + 1) * 4 + 3];
    float d4 = hv.x * l2W[c0] + hv.y * l2W[c0 + 1];
    d0 = wredsum(d0); d1 = wredsum(d1); d2 = wredsum(d2); d3 = wredsum(d3); d4 = wredsum(d4);
    if (lane == 0) {
        g_h2h[g * 4 + 0] = d0; g_h2h[g * 4 + 1] = d1; g_h2h[g * 4 + 2] = d2; g_h2h[g * 4 + 3] = d3;
        g_es2[g * 4 + 0] = d0 * c2as[0]; g_es2[g * 4 + 1] = d1 * c2as[1];
        g_es2[g * 4 + 2] = d2 * c2as[2]; g_es2[g * 4 + 3] = d3 * c2as[3];
        g_ed2[g * 4 + 0] = d0 * c2ad[0]; g_ed2[g * 4 + 1] = d1 * c2ad[1];
        g_ed2[g * 4 + 2] = d2 * c2ad[2]; g_ed2[g * 4 + 3] = d3 * c2ad[3];
        g_lin2[g] = d4;
    }
}

// ---------------- K5: GAT2 aggregation (warp per node, lanes over edges) ----------------
__global__ __launch_bounds__(256) void k5(const float* __restrict__ c2b, const float* __restrict__ l2b) {
    int warp = (blockIdx.x * blockDim.x + threadIdx.x) >> 5;
    if (warp >= G) return;
    int lane = threadIdx.x & 31;
    int g = warp;
    int o = g_off[g];
    int deg = g_off[g + 1] - o;
    float4 ed = *(const float4*)&g_ed2[g * 4];
    float m0 = -1e30f, m1 = -1e30f, m2 = -1e30f, m3 = -1e30f;
    for (int e = lane - 1; e < deg; e += 32) {
        int s = (e < 0) ? g : g_csr[o + e];
        float4 es = *(const float4*)&g_es2[s * 4];
        m0 = fmaxf(m0, lrelu(es.x + ed.x));
        m1 = fmaxf(m1, lrelu(es.y + ed.y));
        m2 = fmaxf(m2, lrelu(es.z + ed.z));
        m3 = fmaxf(m3, lrelu(es.w + ed.w));
    }
    m0 = wredmax(m0); m1 = wredmax(m1); m2 = wredmax(m2); m3 = wredmax(m3);
    float de0 = 0.f, de1 = 0.f, de2 = 0.f, de3 = 0.f;
    float a0 = 0.f, a1 = 0.f, a2 = 0.f, a3 = 0.f;
    for (int e = lane - 1; e < deg; e += 32) {
        int s = (e < 0) ? g : g_csr[o + e];
        float4 es = *(const float4*)&g_es2[s * 4];
        float4 h2 = *(const float4*)&g_h2h[s * 4];
        float x0 = __expf(lrelu(es.x + ed.x) - m0);
        float x1 = __expf(lrelu(es.y + ed.y) - m1);
        float x2 = __expf(lrelu(es.z + ed.z) - m2);
        float x3 = __expf(lrelu(es.w + ed.w) - m3);
        de0 += x0; de1 += x1; de2 += x2; de3 += x3;
        a0 += x0 * h2.x; a1 += x1 * h2.y; a2 += x2 * h2.z; a3 += x3 * h2.w;
    }
    de0 = wredsum(de0); de1 = wredsum(de1); de2 = wredsum(de2); de3 = wredsum(de3);
    a0 = wredsum(a0); a1 = wredsum(a1); a2 = wredsum(a2); a3 = wredsum(a3);
    if (lane == 0) {
        float r = 0.25f * (a0 / de0 + a1 / de1 + a2 / de2 + a3 / de3);
        g_feat[g] = sigmoidf(r + c2b[0] + g_lin2[g] + l2b[0]);
    }
}

// ---------------- K6: pert MLP ----------------
__global__ __launch_bounds__(128) void k6(const float* __restrict__ pert, const float* __restrict__ W1,
                                          const float* __restrict__ b1, const float* __restrict__ W2,
                                          const float* __restrict__ b2) {
    __shared__ float sp[PDIM];
    __shared__ float s1[128];
    int b = blockIdx.x, t = threadIdx.x;
    for (int i = t; i < PDIM; i += 128) sp[i] = pert[b * PDIM + i];
    __syncthreads();
    float a = b1[t];
    for (int k = 0; k < PDIM; k++) a += sp[k] * W1[k * 128 + t];
    s1[t] = sigmoidf(a);
    __syncthreads();
    if (t < 64) {
        float o = b2[t];
        for (int k = 0; k < 128; k++) o += s1[k] * W2[k * 64 + t];
        g_pout[b * 64 + t] = o;
    }
}

// ---------------- GEMM1: (ctrl+feat)[128,20000] @ W1[:20000,1024] split-K ----------------
__global__ __launch_bounds__(256) void gemm1(const float* __restrict__ Ac, const float* __restrict__ Bw) {
    __shared__ float As[32][128];
    __shared__ float Bs[32][64];
    int t = threadIdx.x, tx = t & 15, ty = t >> 4;
    int n0 = blockIdx.x * 64;
    int kb = blockIdx.y;
    int kstart = kb * 1280;
    int kend = min(G, kstart + 1280);
    float c[8][4];
#pragma unroll
    for (int i = 0; i < 8; i++)
#pragma unroll
        for (int j = 0; j < 4; j++) c[i][j] = 0.f;
    for (int kk = kstart; kk < kend; kk += 32) {
#pragma unroll
        for (int i = 0; i < 4; i++) {
            int idx = t + i * 256;
            int row = idx >> 3, kq = idx & 7;
            float4 v = *(const float4*)&Ac[row * G + kk + kq * 4];
            float4 f = *(const float4*)&g_feat[kk + kq * 4];
            As[kq * 4 + 0][row] = v.x + f.x;
            As[kq * 4 + 1][row] = v.y + f.y;
            As[kq * 4 + 2][row] = v.z + f.z;
            As[kq * 4 + 3][row] = v.w + f.w;
        }
#pragma unroll
        for (int i = 0; i < 2; i++) {
            int idx = t + i * 256;
            int row = idx >> 4, cq = idx & 15;
            *(float4*)&Bs[row][cq * 4] = *(const float4*)&Bw[(kk + row) * 1024 + n0 + cq * 4];
        }
        __syncthreads();
#pragma unroll
        for (int k = 0; k < 32; k++) {
            float a[8], bb[4];
            *(float4*)&a[0] = *(const float4*)&As[k][ty * 8];
            *(float4*)&a[4] = *(const float4*)&As[k][ty * 8 + 4];
            *(float4*)&bb[0] = *(const float4*)&Bs[k][tx * 4];
#pragma unroll
            for (int i = 0; i < 8; i++)
#pragma unroll
                for (int j = 0; j < 4; j++) c[i][j] += a[i] * bb[j];
        }
        __syncthreads();
    }
    float* pout = &g_part1[kb * (NB * 1024)];
#pragma unroll
    for (int i = 0; i < 8; i++) {
        int row = ty * 8 + i;
#pragma unroll
        for (int j = 0; j < 4; j++) pout[row * 1024 + n0 + tx * 4 + j] = c[i][j];
    }
}

// ---------------- K8: reduce partials + pert columns + bias + sigmoid ----------------
__global__ __launch_bounds__(256) void k8(const float* __restrict__ W1, const float* __restrict__ b1) {
    __shared__ float sp[NB * 64];
    int t = threadIdx.x;
    int j = blockIdx.x * 256 + t;
    for (int i = t; i < NB * 64; i += 256) sp[i] = g_pout[i];
    float w[64];
#pragma unroll
    for (int k = 0; k < 64; k++) w[k] = W1[(G + k) * 1024 + j];
    __syncthreads();
    float bj = b1[j];
    for (int b = 0; b < NB; b++) {
        float s = bj;
#pragma unroll
        for (int p = 0; p < 16; p++) s += g_part1[p * (NB * 1024) + b * 1024 + j];
#pragma unroll
        for (int k = 0; k < 64; k++) s += sp[b * 64 + k] * w[k];
        g_hid[b * 1024 + j] = sigmoidf(s);
    }
}

// ---------------- GEMM2: hid[128,1024] @ W2[1024,20000] + b2 -> out ----------------
__global__ __launch_bounds__(256) void gemm2(const float* __restrict__ Bw, const float* __restrict__ bias,
                                             float* __restrict__ Co) {
    __shared__ float As[32][128];
    __shared__ float Bs[32][64];
    int t = threadIdx.x, tx = t & 15, ty = t >> 4;
    int n0 = blockIdx.x * 64;
    float c[8][4];
#pragma unroll
    for (int i = 0; i < 8; i++)
#pragma unroll
        for (int j = 0; j < 4; j++) c[i][j] = 0.f;
    for (int kk = 0; kk < 1024; kk += 32) {
#pragma unroll
        for (int i = 0; i < 4; i++) {
            int idx = t + i * 256;
            int row = idx >> 3, kq = idx & 7;
            float4 v = *(const float4*)&g_hid[row * 1024 + kk + kq * 4];
            As[kq * 4 + 0][row] = v.x;
            As[kq * 4 + 1][row] = v.y;
            As[kq * 4 + 2][row] = v.z;
            As[kq * 4 + 3][row] = v.w;
        }
#pragma unroll
        for (int i = 0; i < 2; i++) {
            int idx = t + i * 256;
            int row = idx >> 4, cq = idx & 15;
            int col = n0 + cq * 4;
            float4 v;
            if (col < G) v = *(const float4*)&Bw[(kk + row) * G + col];
            else { v.x = v.y = v.z = v.w = 0.f; }
            *(float4*)&Bs[row][cq * 4] = v;
        }
        __syncthreads();
#pragma unroll
        for (int k = 0; k < 32; k++) {
            float a[8], bb[4];
            *(float4*)&a[0] = *(const float4*)&As[k][ty * 8];
            *(float4*)&a[4] = *(const float4*)&As[k][ty * 8 + 4];
            *(float4*)&bb[0] = *(const float4*)&Bs[k][tx * 4];
#pragma unroll
            for (int i = 0; i < 8; i++)
#pragma unroll
                for (int j = 0; j < 4; j++) c[i][j] += a[i] * bb[j];
        }
        __syncthreads();
    }
#pragma unroll
    for (int i = 0; i < 8; i++) {
        int row = ty * 8 + i;
#pragma unroll
        for (int j = 0; j < 4; j++) {
            int col = n0 + tx * 4 + j;
            if (col < G) Co[row * G + col] = c[i][j] + bias[col];
        }
    }
}

// ---------------- launch ----------------
extern "C" void kernel_launch(void* const* d_in, const int* in_sizes, int n_in,
                              void* d_out, int out_size) {
    const float* x = (const float*)d_in[0];
    const int* ei = (const int*)d_in[1];
    const int* pos = (const int*)d_in[2];
    const float* ctrl = (const float*)d_in[3];
    const float* pert = (const float*)d_in[4];
    const float* ge = (const float*)d_in[5];
    const float* c1W = (const float*)d_in[6];
    const float* c1as = (const float*)d_in[7];
    const float* c1ad = (const float*)d_in[8];
    const float* c1b = (const float*)d_in[9];
    const float* l1W = (const float*)d_in[10];
    const float* l1b = (const float*)d_in[11];
    const float* c2W = (const float*)d_in[12];
    const float* c2as = (const float*)d_in[13];
    const float* c2ad = (const float*)d_in[14];
    const float* c2b = (const float*)d_in[15];
    const float* l2W = (const float*)d_in[16];
    const float* l2b = (const float*)d_in[17];
    const float* pW1 = (const float*)d_in[18];
    const float* pb1 = (const float*)d_in[19];
    const float* pW2 = (const float*)d_in[20];
    const float* pb2 = (const float*)d_in[21];
    const float* prW1 = (const float*)d_in[22];
    const float* prb1 = (const float*)d_in[23];
    const float* prW2 = (const float*)d_in[24];
    const float* prb2 = (const float*)d_in[25];
    float* out = (float*)d_out;

    k_zero_deg<<<(G + 255) / 256, 256>>>();
    k_hist<<<(NE + 255) / 256, 256>>>(ei);
    k_scan<<<1, 1024>>>();
    k_scatter<<<(NE + 255) / 256, 256>>>(ei);
    k1<<<dim3(512, 2), 128>>>(x, pos, ge, c1W, c1as, c1ad, l1W, l1b);
    k3<<<(G * 32 + 255) / 256, 256>>>(c1b);
    k4<<<(G * 32 + 255) / 256, 256>>>(c2W, c2as, c2ad, l2W);
    k5<<<(G * 32 + 255) / 256, 256>>>(c2b, l2b);
    k6<<<NB, 128>>>(pert, pW1, pb1, pW2, pb2);
    gemm1<<<dim3(16, 16), 256>>>(ctrl, prW1);
    k8<<<4, 256>>>(prW1, prb1);
    gemm2<<<313, 256>>>(prW2, prb2, out);
}

// round 2
// speedup vs baseline: 1.4454x; 1.4454x over previous
#include <cuda_runtime.h>
#include <cuda_bf16.h>
#include <mma.h>

#define G 20000
#define NH 4
#define NE 640000
#define NB 128
#define PDIM 600

// ---------------- scratch (static device globals; no runtime alloc) ----------------
__device__ __align__(16) float g_h[G * 256];       // conv1 per-node features (N,4,64)
__device__ __align__(16) float g_es1[G * 4];
__device__ __align__(16) float g_ed1[G * 4];
__device__ __align__(16) float g_lin1[G * 64];     // xc @ lin1_W + lin1_b
__device__ __align__(16) float g_h1[G * 64];
__device__ __align__(16) float g_h2h[G * 4];
__device__ __align__(16) float g_es2[G * 4];
__device__ __align__(16) float g_ed2[G * 4];
__device__ __align__(16) float g_lin2[G];
__device__ __align__(16) float g_feat[G];
__device__ int g_deg[G];
__device__ int g_off[G + 1];
__device__ int g_cur[G];
__device__ int g_csr[NE];
__device__ __align__(16) float g_pout[NB * 64];
__device__ __align__(16) float g_part1[16 * NB * 1024];  // GEMM1 split-K partials
__device__ __align__(16) __nv_bfloat16 g_hid_hi[NB * 1024];
__device__ __align__(16) __nv_bfloat16 g_hid_lo[NB * 1024];

// ---------------- helpers ----------------
__device__ __forceinline__ float lrelu(float v) { return v > 0.f ? v : 0.2f * v; }
__device__ __forceinline__ float sigmoidf(float v) { return 1.f / (1.f + __expf(-v)); }
__device__ __forceinline__ float wredmax(float v) {
#pragma unroll
    for (int o = 16; o; o >>= 1) v = fmaxf(v, __shfl_xor_sync(0xFFFFFFFFu, v, o));
    return v;
}
__device__ __forceinline__ float wredsum(float v) {
#pragma unroll
    for (int o = 16; o; o >>= 1) v += __shfl_xor_sync(0xFFFFFFFFu, v, o);
    return v;
}
__device__ __forceinline__ void split2(float x, __nv_bfloat16& h, __nv_bfloat16& l) {
    h = __float2bfloat16(x);
    l = __float2bfloat16(x - __bfloat162float(h));
}

// ---------------- CSR build ----------------
__global__ void k_zero_deg() {
    int i = blockIdx.x * blockDim.x + threadIdx.x;
    if (i < G) g_deg[i] = 0;
}
__global__ void k_hist(const int* __restrict__ ei) {
    int i = blockIdx.x * blockDim.x + threadIdx.x;
    if (i < NE) atomicAdd(&g_deg[ei[NE + i]], 1);
}
__global__ void k_scan() {   // single block, 1024 threads
    __shared__ int s[1024];
    int tid = threadIdx.x;
    int carry = 0;
    for (int base = 0; base < G; base += 1024) {
        int v = (base + tid < G) ? g_deg[base + tid] : 0;
        s[tid] = v;
        __syncthreads();
        for (int d = 1; d < 1024; d <<= 1) {
            int t2 = (tid >= d) ? s[tid - d] : 0;
            __syncthreads();
            s[tid] += t2;
            __syncthreads();
        }
        int incl = s[tid];
        if (base + tid < G) {
            g_off[base + tid + 1] = carry + incl;
            g_cur[base + tid] = carry + incl - v;
        }
        int tot = s[1023];
        __syncthreads();
        carry += tot;
    }
    if (tid == 0) g_off[0] = 0;
}
__global__ void k_scatter(const int* __restrict__ ei) {
    int i = blockIdx.x * blockDim.x + threadIdx.x;
    if (i < NE) {
        int d = ei[NE + i];
        int s = ei[i];
        int p = atomicAdd(&g_cur[d], 1);
        g_csr[p] = s;
    }
}

// ---------------- K1: conv1 features, attn scalars, lin1 ----------------
__global__ __launch_bounds__(128) void k1(const float* __restrict__ x, const int* __restrict__ pos,
                                          const float* __restrict__ ge, const float* __restrict__ W,
                                          const float* __restrict__ as_, const float* __restrict__ ad_,
                                          const float* __restrict__ linW, const float* __restrict__ linb) {
    __shared__ float sW[65 * 128];
    __shared__ float sES[65 * 2], sED[65 * 2];
    __shared__ float sx[65];
    int t = threadIdx.x;
    int half = blockIdx.y;
    int cbase = half * 128;
    for (int i = t; i < 65 * 128; i += 128) {
        int k = i >> 7, c = i & 127;
        sW[i] = W[k * 256 + cbase + c];
    }
    __syncthreads();
    for (int i = t; i < 65 * 2; i += 128) {
        int k = i >> 1, hh = i & 1;
        int h = half * 2 + hh;
        float s = 0.f, d = 0.f;
        for (int c = 0; c < 64; c++) {
            float w = sW[k * 128 + hh * 64 + c];
            s += w * as_[h * 64 + c];
            d += w * ad_[h * 64 + c];
        }
        sES[i] = s;
        sED[i] = d;
    }
    __syncthreads();
    for (int g = blockIdx.x; g < G; g += gridDim.x) {
        if (t == 0) sx[0] = x[g];
        else if (t < 65) sx[t] = ge[pos[g] * 64 + t - 1];
        __syncthreads();
        float acc = 0.f;
#pragma unroll 13
        for (int k = 0; k < 65; k++) acc += sx[k] * sW[k * 128 + t];
        g_h[g * 256 + cbase + t] = acc;
        if (half == 0 && t < 64) {
            float l = linb[t];
            for (int k = 0; k < 65; k++) l += sx[k] * linW[k * 64 + t];
            g_lin1[g * 64 + t] = l;
        }
        if (t < 2) {
            int h = half * 2 + t;
            float s = 0.f, d = 0.f;
            for (int k = 0; k < 65; k++) {
                s += sx[k] * sES[k * 2 + t];
                d += sx[k] * sED[k * 2 + t];
            }
            g_es1[g * 4 + h] = s;
            g_ed1[g * 4 + h] = d;
        }
        __syncthreads();
    }
}

// ---------------- K3: GAT1 aggregation (one warp per node, pipelined) ----------------
__global__ __launch_bounds__(256) void k3(const float* __restrict__ conv1_b) {
    int warp = (blockIdx.x * blockDim.x + threadIdx.x) >> 5;
    if (warp >= G) return;
    int lane = threadIdx.x & 31;
    int g = warp;
    int o = g_off[g];
    int deg = g_off[g + 1] - o;
    float4 ed = *(const float4*)&g_ed1[g * 4];

    // pass 1: per-head max over edges + self loop (lanes over edges)
    float m0 = -1e30f, m1 = -1e30f, m2 = -1e30f, m3 = -1e30f;
    for (int e = lane - 1; e < deg; e += 32) {
        int s = (e < 0) ? g : g_csr[o + e];
        float4 es = *(const float4*)&g_es1[s * 4];
        m0 = fmaxf(m0, lrelu(es.x + ed.x));
        m1 = fmaxf(m1, lrelu(es.y + ed.y));
        m2 = fmaxf(m2, lrelu(es.z + ed.z));
        m3 = fmaxf(m3, lrelu(es.w + ed.w));
    }
    m0 = wredmax(m0); m1 = wredmax(m1); m2 = wredmax(m2); m3 = wredmax(m3);

    // pass 2: edge-serial, lanes over channels, 1-deep software pipeline on csr+es
    int c0 = lane * 2;
    float2 a0 = {0.f, 0.f}, a1 = {0.f, 0.f}, a2 = {0.f, 0.f}, a3 = {0.f, 0.f};
    float d0 = 0.f, d1 = 0.f, d2 = 0.f, d3 = 0.f;
    int s_cur = g;
    float4 es_cur = *(const float4*)&g_es1[g * 4];
    for (int e = -1; e < deg; e++) {
        int s_nxt = (e + 1 < deg) ? g_csr[o + e + 1] : 0;
        float4 es_nxt = *(const float4*)&g_es1[s_nxt * 4];
        float x0 = __expf(lrelu(es_cur.x + ed.x) - m0);
        float x1 = __expf(lrelu(es_cur.y + ed.y) - m1);
        float x2 = __expf(lrelu(es_cur.z + ed.z) - m2);
        float x3 = __expf(lrelu(es_cur.w + ed.w) - m3);
        d0 += x0; d1 += x1; d2 += x2; d3 += x3;
        const float* hb = &g_h[s_cur * 256 + c0];
        float2 v0 = *(const float2*)(hb);
        float2 v1 = *(const float2*)(hb + 64);
        float2 v2 = *(const float2*)(hb + 128);
        float2 v3 = *(const float2*)(hb + 192);
        a0.x += x0 * v0.x; a0.y += x0 * v0.y;
        a1.x += x1 * v1.x; a1.y += x1 * v1.y;
        a2.x += x2 * v2.x; a2.y += x2 * v2.y;
        a3.x += x3 * v3.x; a3.y += x3 * v3.y;
        s_cur = s_nxt;
        es_cur = es_nxt;
    }
    float i0 = 1.f / d0, i1 = 1.f / d1, i2 = 1.f / d2, i3 = 1.f / d3;
    float o0 = 0.25f * (a0.x * i0 + a1.x * i1 + a2.x * i2 + a3.x * i3)
             + conv1_b[c0] + g_lin1[g * 64 + c0];
    float o1 = 0.25f * (a0.y * i0 + a1.y * i1 + a2.y * i2 + a3.y * i3)
             + conv1_b[c0 + 1] + g_lin1[g * 64 + c0 + 1];
    float2 r;
    r.x = sigmoidf(o0);
    r.y = sigmoidf(o1);
    *(float2*)&g_h1[g * 64 + c0] = r;
}

// ---------------- K4: layer-2 per-node projections ----------------
__global__ __launch_bounds__(256) void k4(const float* __restrict__ c2W, const float* __restrict__ c2as,
                                          const float* __restrict__ c2ad, const float* __restrict__ l2W) {
    int warp = (blockIdx.x * blockDim.x + threadIdx.x) >> 5;
    if (warp >= G) return;
    int lane = threadIdx.x & 31;
    int g = warp;
    int c0 = lane * 2;
    float2 hv = *(const float2*)&g_h1[g * 64 + c0];
    float d0 = hv.x * c2W[c0 * 4 + 0] + hv.y * c2W[(c0 + 1) * 4 + 0];
    float d1 = hv.x * c2W[c0 * 4 + 1] + hv.y * c2W[(c0 + 1) * 4 + 1];
    float d2 = hv.x * c2W[c0 * 4 + 2] + hv.y * c2W[(c0 + 1) * 4 + 2];
    float d3 = hv.x * c2W[c0 * 4 + 3] + hv.y * c2W[(c0 + 1) * 4 + 3];
    float d4 = hv.x * l2W[c0] + hv.y * l2W[c0 + 1];
    d0 = wredsum(d0); d1 = wredsum(d1); d2 = wredsum(d2); d3 = wredsum(d3); d4 = wredsum(d4);
    if (lane == 0) {
        g_h2h[g * 4 + 0] = d0; g_h2h[g * 4 + 1] = d1; g_h2h[g * 4 + 2] = d2; g_h2h[g * 4 + 3] = d3;
        g_es2[g * 4 + 0] = d0 * c2as[0]; g_es2[g * 4 + 1] = d1 * c2as[1];
        g_es2[g * 4 + 2] = d2 * c2as[2]; g_es2[g * 4 + 3] = d3 * c2as[3];
        g_ed2[g * 4 + 0] = d0 * c2ad[0]; g_ed2[g * 4 + 1] = d1 * c2ad[1];
        g_ed2[g * 4 + 2] = d2 * c2ad[2]; g_ed2[g * 4 + 3] = d3 * c2ad[3];
        g_lin2[g] = d4;
    }
}

// ---------------- K5: GAT2 aggregation (warp per node, lanes over edges) ----------------
__global__ __launch_bounds__(256) void k5(const float* __restrict__ c2b, const float* __restrict__ l2b) {
    int warp = (blockIdx.x * blockDim.x + threadIdx.x) >> 5;
    if (warp >= G) return;
    int lane = threadIdx.x & 31;
    int g = warp;
    int o = g_off[g];
    int deg = g_off[g + 1] - o;
    float4 ed = *(const float4*)&g_ed2[g * 4];
    float m0 = -1e30f, m1 = -1e30f, m2 = -1e30f, m3 = -1e30f;
    for (int e = lane - 1; e < deg; e += 32) {
        int s = (e < 0) ? g : g_csr[o + e];
        float4 es = *(const float4*)&g_es2[s * 4];
        m0 = fmaxf(m0, lrelu(es.x + ed.x));
        m1 = fmaxf(m1, lrelu(es.y + ed.y));
        m2 = fmaxf(m2, lrelu(es.z + ed.z));
        m3 = fmaxf(m3, lrelu(es.w + ed.w));
    }
    m0 = wredmax(m0); m1 = wredmax(m1); m2 = wredmax(m2); m3 = wredmax(m3);
    float de0 = 0.f, de1 = 0.f, de2 = 0.f, de3 = 0.f;
    float a0 = 0.f, a1 = 0.f, a2 = 0.f, a3 = 0.f;
    for (int e = lane - 1; e < deg; e += 32) {
        int s = (e < 0) ? g : g_csr[o + e];
        float4 es = *(const float4*)&g_es2[s * 4];
        float4 h2 = *(const float4*)&g_h2h[s * 4];
        float x0 = __expf(lrelu(es.x + ed.x) - m0);
        float x1 = __expf(lrelu(es.y + ed.y) - m1);
        float x2 = __expf(lrelu(es.z + ed.z) - m2);
        float x3 = __expf(lrelu(es.w + ed.w) - m3);
        de0 += x0; de1 += x1; de2 += x2; de3 += x3;
        a0 += x0 * h2.x; a1 += x1 * h2.y; a2 += x2 * h2.z; a3 += x3 * h2.w;
    }
    de0 = wredsum(de0); de1 = wredsum(de1); de2 = wredsum(de2); de3 = wredsum(de3);
    a0 = wredsum(a0); a1 = wredsum(a1); a2 = wredsum(a2); a3 = wredsum(a3);
    if (lane == 0) {
        float r = 0.25f * (a0 / de0 + a1 / de1 + a2 / de2 + a3 / de3);
        g_feat[g] = sigmoidf(r + c2b[0] + g_lin2[g] + l2b[0]);
    }
}

// ---------------- K6: pert MLP ----------------
__global__ __launch_bounds__(128) void k6(const float* __restrict__ pert, const float* __restrict__ W1,
                                          const float* __restrict__ b1, const float* __restrict__ W2,
                                          const float* __restrict__ b2) {
    __shared__ float sp[PDIM];
    __shared__ float s1[128];
    int b = blockIdx.x, t = threadIdx.x;
    for (int i = t; i < PDIM; i += 128) sp[i] = pert[b * PDIM + i];
    __syncthreads();
    float a = b1[t];
    for (int k = 0; k < PDIM; k++) a += sp[k] * W1[k * 128 + t];
    s1[t] = sigmoidf(a);
    __syncthreads();
    if (t < 64) {
        float o = b2[t];
        for (int k = 0; k < 128; k++) o += s1[k] * W2[k * 64 + t];
        g_pout[b * 64 + t] = o;
    }
}

// ---------------- GEMM1 (tensor cores, bf16 split): partials to g_part1 ----------------
// C[128,1024] += (ctrl+feat)[128, Kslice] @ W1[Kslice, 1024], splitK = 16
__global__ __launch_bounds__(256) void gemm1_tc(const float* __restrict__ ctrl,
                                                const float* __restrict__ W1) {
    using namespace nvcuda;
    __shared__ __align__(16) __nv_bfloat16 sAh[128 * 48], sAl[128 * 48];
    __shared__ __align__(16) __nv_bfloat16 sBh[32 * 72], sBl[32 * 72];
    int t = threadIdx.x;
    int n0 = blockIdx.x * 64;
    int sk = blockIdx.y;
    int cb = (sk * 625) >> 4, ce = ((sk + 1) * 625) >> 4;
    int warp = t >> 5, wm = warp & 3, wn = warp >> 2;

    wmma::fragment<wmma::accumulator, 16, 16, 16, float> acc[2][2];
#pragma unroll
    for (int mi = 0; mi < 2; mi++)
#pragma unroll
        for (int ni = 0; ni < 2; ni++) wmma::fill_fragment(acc[mi][ni], 0.f);

    float4 ra[4];
    float4 rb[2];

    auto loadAB = [&](int kk) {
#pragma unroll
        for (int i = 0; i < 4; i++) {
            int lin = t + i * 256;
            int b = lin >> 3, kq = lin & 7;
            int k = kk + kq * 4;
            float4 c4 = *(const float4*)&ctrl[b * G + k];
            float4 f4 = *(const float4*)&g_feat[k];
            ra[i].x = c4.x + f4.x; ra[i].y = c4.y + f4.y;
            ra[i].z = c4.z + f4.z; ra[i].w = c4.w + f4.w;
        }
#pragma unroll
        for (int i = 0; i < 2; i++) {
            int lin = t + i * 256;
            int r = lin >> 4, cq = lin & 15;
            rb[i] = *(const float4*)&W1[(kk + r) * 1024 + n0 + cq * 4];
        }
    };
    auto storeAB = [&]() {
#pragma unroll
        for (int i = 0; i < 4; i++) {
            int lin = t + i * 256;
            int b = lin >> 3, kq = lin & 7;
            const float* v = (const float*)&ra[i];
#pragma unroll
            for (int j = 0; j < 4; j++) {
                __nv_bfloat16 h, l;
                split2(v[j], h, l);
                sAh[b * 48 + kq * 4 + j] = h;
                sAl[b * 48 + kq * 4 + j] = l;
            }
        }
#pragma unroll
        for (int i = 0; i < 2; i++) {
            int lin = t + i * 256;
            int r = lin >> 4, cq = lin & 15;
            const float* v = (const float*)&rb[i];
#pragma unroll
            for (int j = 0; j < 4; j++) {
                __nv_bfloat16 h, l;
                split2(v[j], h, l);
                sBh[r * 72 + cq * 4 + j] = h;
                sBl[r * 72 + cq * 4 + j] = l;
            }
        }
    };

    loadAB(cb * 32);
    for (int c = cb; c < ce; c++) {
        storeAB();
        __syncthreads();
        if (c + 1 < ce) loadAB((c + 1) * 32);
#pragma unroll
        for (int ks = 0; ks < 2; ks++) {
            wmma::fragment<wmma::matrix_a, 16, 16, 16, __nv_bfloat16, wmma::row_major> ah[2], al[2];
            wmma::fragment<wmma::matrix_b, 16, 16, 16, __nv_bfloat16, wmma::row_major> bh[2], bl[2];
#pragma unroll
            for (int mi = 0; mi < 2; mi++) {
                wmma::load_matrix_sync(ah[mi], &sAh[(wm * 32 + mi * 16) * 48 + ks * 16], 48);
                wmma::load_matrix_sync(al[mi], &sAl[(wm * 32 + mi * 16) * 48 + ks * 16], 48);
            }
#pragma unroll
            for (int ni = 0; ni < 2; ni++) {
                wmma::load_matrix_sync(bh[ni], &sBh[(ks * 16) * 72 + wn * 32 + ni * 16], 72);
                wmma::load_matrix_sync(bl[ni], &sBl[(ks * 16) * 72 + wn * 32 + ni * 16], 72);
            }
#pragma unroll
            for (int mi = 0; mi < 2; mi++)
#pragma unroll
                for (int ni = 0; ni < 2; ni++) {
                    wmma::mma_sync(acc[mi][ni], ah[mi], bh[ni], acc[mi][ni]);
                    wmma::mma_sync(acc[mi][ni], ah[mi], bl[ni], acc[mi][ni]);
                    wmma::mma_sync(acc[mi][ni], al[mi], bh[ni], acc[mi][ni]);
                }
        }
        __syncthreads();
    }
    float* pout = g_part1 + sk * (NB * 1024);
#pragma unroll
    for (int mi = 0; mi < 2; mi++)
#pragma unroll
        for (int ni = 0; ni < 2; ni++)
            wmma::store_matrix_sync(&pout[(wm * 32 + mi * 16) * 1024 + n0 + wn * 32 + ni * 16],
                                    acc[mi][ni], 1024, wmma::mem_row_major);
}

// ---------------- K8: reduce partials + pert columns + bias + sigmoid -> bf16 hid ----------------
__global__ __launch_bounds__(256) void k8(const float* __restrict__ W1, const float* __restrict__ b1) {
    __shared__ float sp[16 * 64];
    int t = threadIdx.x;
    int j = blockIdx.x * 256 + t;
    int b0 = blockIdx.y * 16;
    for (int i = t; i < 16 * 64; i += 256) sp[i] = g_pout[(b0 + (i >> 6)) * 64 + (i & 63)];
    float w[64];
#pragma unroll
    for (int k = 0; k < 64; k++) w[k] = W1[(G + k) * 1024 + j];
    __syncthreads();
    float bj = b1[j];
    for (int bi = 0; bi < 16; bi++) {
        int b = b0 + bi;
        float s = bj;
#pragma unroll
        for (int p = 0; p < 16; p++) s += g_part1[p * (NB * 1024) + b * 1024 + j];
#pragma unroll
        for (int k = 0; k < 64; k++) s += sp[bi * 64 + k] * w[k];
        float v = sigmoidf(s);
        __nv_bfloat16 h, l;
        split2(v, h, l);
        g_hid_hi[b * 1024 + j] = h;
        g_hid_lo[b * 1024 + j] = l;
    }
}

// ---------------- GEMM2 (tensor cores): out = hid[128,1024] @ W2[1024,20000] + b2 ----------------
__global__ __launch_bounds__(256) void gemm2_tc(const float* __restrict__ Bw,
                                                const float* __restrict__ bias,
                                                float* __restrict__ Co) {
    using namespace nvcuda;
    __shared__ __align__(16) char pool[128 * 72 * 4];   // 36864 bytes
    __nv_bfloat16* sAh = (__nv_bfloat16*)pool;                 // 128*48
    __nv_bfloat16* sAl = sAh + 128 * 48;                       // 128*48
    __nv_bfloat16* sBh = (__nv_bfloat16*)(pool + 24576);       // 32*72
    __nv_bfloat16* sBl = sBh + 32 * 72;                        // ends at 33792
    float* sOut = (float*)pool;                                // reused in epilogue

    int t = threadIdx.x;
    int n0 = blockIdx.x * 64;
    int warp = t >> 5, wm = warp & 3, wn = warp >> 2;

    wmma::fragment<wmma::accumulator, 16, 16, 16, float> acc[2][2];
#pragma unroll
    for (int mi = 0; mi < 2; mi++)
#pragma unroll
        for (int ni = 0; ni < 2; ni++) wmma::fill_fragment(acc[mi][ni], 0.f);

    uint4 rah[2], ral[2];
    float4 rb[2];

    auto loadAB = [&](int kk) {
#pragma unroll
        for (int i = 0; i < 2; i++) {
            int lin = t + i * 256;
            int b = lin >> 2, kq = lin & 3;
            int k = kk + kq * 8;
            rah[i] = *(const uint4*)&g_hid_hi[b * 1024 + k];
            ral[i] = *(const uint4*)&g_hid_lo[b * 1024 + k];
        }
#pragma unroll
        for (int i = 0; i < 2; i++) {
            int lin = t + i * 256;
            int r = lin >> 4, cq = lin & 15;
            int col = n0 + cq * 4;
            if (col < G) rb[i] = *(const float4*)&Bw[(kk + r) * G + col];
            else { rb[i].x = rb[i].y = rb[i].z = rb[i].w = 0.f; }
        }
    };
    auto storeAB = [&]() {
#pragma unroll
        for (int i = 0; i < 2; i++) {
            int lin = t + i * 256;
            int b = lin >> 2, kq = lin & 3;
            *(uint4*)&sAh[b * 48 + kq * 8] = rah[i];
            *(uint4*)&sAl[b * 48 + kq * 8] = ral[i];
        }
#pragma unroll
        for (int i = 0; i < 2; i++) {
            int lin = t + i * 256;
            int r = lin >> 4, cq = lin & 15;
            const float* v = (const float*)&rb[i];
#pragma unroll
            for (int j = 0; j < 4; j++) {
                __nv_bfloat16 h, l;
                split2(v[j], h, l);
                sBh[r * 72 + cq * 4 + j] = h;
                sBl[r * 72 + cq * 4 + j] = l;
            }
        }
    };

    loadAB(0);
    for (int c = 0; c < 32; c++) {
        storeAB();
        __syncthreads();
        if (c + 1 < 32) loadAB((c + 1) * 32);
#pragma unroll
        for (int ks = 0; ks < 2; ks++) {
            wmma::fragment<wmma::matrix_a, 16, 16, 16, __nv_bfloat16, wmma::row_major> ah[2], al[2];
            wmma::fragment<wmma::matrix_b, 16, 16, 16, __nv_bfloat16, wmma::row_major> bh[2], bl[2];
#pragma unroll
            for (int mi = 0; mi < 2; mi++) {
                wmma::load_matrix_sync(ah[mi], &sAh[(wm * 32 + mi * 16) * 48 + ks * 16], 48);
                wmma::load_matrix_sync(al[mi], &sAl[(wm * 32 + mi * 16) * 48 + ks * 16], 48);
            }
#pragma unroll
            for (int ni = 0; ni < 2; ni++) {
                wmma::load_matrix_sync(bh[ni], &sBh[(ks * 16) * 72 + wn * 32 + ni * 16], 72);
                wmma::load_matrix_sync(bl[ni], &sBl[(ks * 16) * 72 + wn * 32 + ni * 16], 72);
            }
#pragma unroll
            for (int mi = 0; mi < 2; mi++)
#pragma unroll
                for (int ni = 0; ni < 2; ni++) {
                    wmma::mma_sync(acc[mi][ni], ah[mi], bh[ni], acc[mi][ni]);
                    wmma::mma_sync(acc[mi][ni], ah[mi], bl[ni], acc[mi][ni]);
                    wmma::mma_sync(acc[mi][ni], al[mi], bh[ni], acc[mi][ni]);
                }
        }
        __syncthreads();
    }

    // epilogue: stage to smem (reusing pool), add bias, write coalesced
#pragma unroll
    for (int mi = 0; mi < 2; mi++)
#pragma unroll
        for (int ni = 0; ni < 2; ni++)
            wmma::store_matrix_sync(&sOut[(wm * 32 + mi * 16) * 72 + wn * 32 + ni * 16],
                                    acc[mi][ni], 72, wmma::mem_row_major);
    __syncthreads();
#pragma unroll
    for (int i = 0; i < 8; i++) {
        int lin = t + i * 256;
        int row = lin >> 4;
        int c4 = (lin & 15) * 4;
        int col = n0 + c4;
        if (col < G) {
            float4 v = *(const float4*)&sOut[row * 72 + c4];
            float4 bb = *(const float4*)&bias[col];
            v.x += bb.x; v.y += bb.y; v.z += bb.z; v.w += bb.w;
            *(float4*)&Co[row * G + col] = v;
        }
    }
}

// ---------------- launch ----------------
extern "C" void kernel_launch(void* const* d_in, const int* in_sizes, int n_in,
                              void* d_out, int out_size) {
    const float* x = (const float*)d_in[0];
    const int* ei = (const int*)d_in[1];
    const int* pos = (const int*)d_in[2];
    const float* ctrl = (const float*)d_in[3];
    const float* pert = (const float*)d_in[4];
    const float* ge = (const float*)d_in[5];
    const float* c1W = (const float*)d_in[6];
    const float* c1as = (const float*)d_in[7];
    const float* c1ad = (const float*)d_in[8];
    const float* c1b = (const float*)d_in[9];
    const float* l1W = (const float*)d_in[10];
    const float* l1b = (const float*)d_in[11];
    const float* c2W = (const float*)d_in[12];
    const float* c2as = (const float*)d_in[13];
    const float* c2ad = (const float*)d_in[14];
    const float* c2b = (const float*)d_in[15];
    const float* l2W = (const float*)d_in[16];
    const float* l2b = (const float*)d_in[17];
    const float* pW1 = (const float*)d_in[18];
    const float* pb1 = (const float*)d_in[19];
    const float* pW2 = (const float*)d_in[20];
    const float* pb2 = (const float*)d_in[21];
    const float* prW1 = (const float*)d_in[22];
    const float* prb1 = (const float*)d_in[23];
    const float* prW2 = (const float*)d_in[24];
    const float* prb2 = (const float*)d_in[25];
    float* out = (float*)d_out;

    k_zero_deg<<<(G + 255) / 256, 256>>>();
    k_hist<<<(NE + 255) / 256, 256>>>(ei);
    k_scan<<<1, 1024>>>();
    k_scatter<<<(NE + 255) / 256, 256>>>(ei);
    k1<<<dim3(512, 2), 128>>>(x, pos, ge, c1W, c1as, c1ad, l1W, l1b);
    k3<<<(G * 32 + 255) / 256, 256>>>(c1b);
    k4<<<(G * 32 + 255) / 256, 256>>>(c2W, c2as, c2ad, l2W);
    k5<<<(G * 32 + 255) / 256, 256>>>(c2b, l2b);
    k6<<<NB, 128>>>(pert, pW1, pb1, pW2, pb2);
    gemm1_tc<<<dim3(16, 16), 256>>>(ctrl, prW1);
    k8<<<dim3(4, 8), 256>>>(prW1, prb1);
    gemm2_tc<<<313, 256>>>(prW2, prb2, out);
}

// round 3
// speedup vs baseline: 1.6604x; 1.1488x over previous
#include <cuda_runtime.h>
#include <cuda_bf16.h>
#include <mma.h>

#define G 20000
#define NH 4
#define NE 640000
#define NB 128
#define PDIM 600

// ---------------- scratch (static device globals; no runtime alloc) ----------------
__device__ __align__(16) unsigned int g_hb16[G * 128];  // conv1 features bf16x2, [g][pair][head]
__device__ __align__(16) float g_es1[G * 4];
__device__ __align__(16) float g_ed1[G * 4];
__device__ __align__(16) float g_lin1[G * 64];
__device__ __align__(16) float g_h1[G * 64];
__device__ __align__(16) float g_pack2[G * 8];          // {es2[4], h2h[4]}
__device__ __align__(16) float g_ed2[G * 4];
__device__ __align__(16) float g_lin2[G];
__device__ __align__(16) float g_feat[G];
__device__ int g_deg[G];
__device__ int g_off[G + 1];
__device__ int g_cur[G];
__device__ int g_csr[NE];
__device__ __align__(16) float g_pout[NB * 64];
__device__ __align__(16) float g_part1[16 * NB * 1024];
__device__ __align__(16) __nv_bfloat16 g_hid_hi[NB * 1024];
__device__ __align__(16) __nv_bfloat16 g_hid_lo[NB * 1024];

// ---------------- helpers ----------------
__device__ __forceinline__ float lrelu(float v) { return v > 0.f ? v : 0.2f * v; }
__device__ __forceinline__ float sigmoidf(float v) { return 1.f / (1.f + __expf(-v)); }
__device__ __forceinline__ float eexp(float v) { return __expf(fminf(v, 60.f)); }
__device__ __forceinline__ float wredsum(float v) {
#pragma unroll
    for (int o = 16; o; o >>= 1) v += __shfl_xor_sync(0xFFFFFFFFu, v, o);
    return v;
}
__device__ __forceinline__ void split2(float x, __nv_bfloat16& h, __nv_bfloat16& l) {
    h = __float2bfloat16(x);
    l = __float2bfloat16(x - __bfloat162float(h));
}

// ---------------- CSR build ----------------
__global__ void k_zero_deg() {
    int i = blockIdx.x * blockDim.x + threadIdx.x;
    if (i < G) g_deg[i] = 0;
}
__global__ void k_hist(const int* __restrict__ ei) {
    int i = blockIdx.x * blockDim.x + threadIdx.x;
    if (i * 4 < NE) {
        int4 d4 = *(const int4*)&ei[NE + i * 4];
        atomicAdd(&g_deg[d4.x], 1);
        atomicAdd(&g_deg[d4.y], 1);
        atomicAdd(&g_deg[d4.z], 1);
        atomicAdd(&g_deg[d4.w], 1);
    }
}
__global__ __launch_bounds__(1024) void k_scan() {   // single block, warp-shuffle scan
    __shared__ int wsum[33];
    int tid = threadIdx.x, lane = tid & 31, w = tid >> 5;
    int carry = 0;
    for (int base = 0; base < G; base += 1024) {
        int i = base + tid;
        int v = (i < G) ? g_deg[i] : 0;
        int inc = v;
#pragma unroll
        for (int o = 1; o < 32; o <<= 1) {
            int t2 = __shfl_up_sync(0xFFFFFFFFu, inc, o);
            if (lane >= o) inc += t2;
        }
        if (lane == 31) wsum[w] = inc;
        __syncthreads();
        if (w == 0) {
            int ws = wsum[lane];
            int sc = ws;
#pragma unroll
            for (int o = 1; o < 32; o <<= 1) {
                int t2 = __shfl_up_sync(0xFFFFFFFFu, sc, o);
                if (lane >= o) sc += t2;
            }
            wsum[lane] = sc - ws;           // exclusive warp prefix
            if (lane == 31) wsum[32] = sc;  // block total
        }
        __syncthreads();
        int incl = carry + wsum[w] + inc;
        if (i < G) {
            g_off[i + 1] = incl;
            g_cur[i] = incl - v;
        }
        carry += wsum[32];
        __syncthreads();
    }
    if (tid == 0) g_off[0] = 0;
}
__global__ void k_scatter(const int* __restrict__ ei) {
    int i = blockIdx.x * blockDim.x + threadIdx.x;
    if (i * 4 < NE) {
        int4 s4 = *(const int4*)&ei[i * 4];
        int4 d4 = *(const int4*)&ei[NE + i * 4];
        int p;
        p = atomicAdd(&g_cur[d4.x], 1); g_csr[p] = s4.x;
        p = atomicAdd(&g_cur[d4.y], 1); g_csr[p] = s4.y;
        p = atomicAdd(&g_cur[d4.z], 1); g_csr[p] = s4.z;
        p = atomicAdd(&g_cur[d4.w], 1); g_csr[p] = s4.w;
    }
}

// ---------------- K1: conv1 features (bf16 packed), attn scalars, lin1 ----------------
__global__ __launch_bounds__(128) void k1(const float* __restrict__ x, const int* __restrict__ pos,
                                          const float* __restrict__ ge, const float* __restrict__ W,
                                          const float* __restrict__ as_, const float* __restrict__ ad_,
                                          const float* __restrict__ linW, const float* __restrict__ linb) {
    __shared__ float sW[65 * 128];
    __shared__ float sES[65 * 2], sED[65 * 2];
    __shared__ float sx[65];
    int t = threadIdx.x;
    int half = blockIdx.y;
    int cbase = half * 128;
    for (int i = t; i < 65 * 128; i += 128) {
        int k = i >> 7, c = i & 127;
        sW[i] = W[k * 256 + cbase + c];
    }
    __syncthreads();
    for (int i = t; i < 65 * 2; i += 128) {
        int k = i >> 1, hh = i & 1;
        int h = half * 2 + hh;
        float s = 0.f, d = 0.f;
        for (int c = 0; c < 64; c++) {
            float w = sW[k * 128 + hh * 64 + c];
            s += w * as_[h * 64 + c];
            d += w * ad_[h * 64 + c];
        }
        sES[i] = s;
        sED[i] = d;
    }
    __syncthreads();
    for (int g = blockIdx.x; g < G; g += gridDim.x) {
        if (t == 0) sx[0] = x[g];
        else if (t < 65) sx[t] = ge[pos[g] * 64 + t - 1];
        __syncthreads();
        float acc = 0.f;
#pragma unroll 13
        for (int k = 0; k < 65; k++) acc += sx[k] * sW[k * 128 + t];
        // pack pairs (even c gets its own + neighbor's value)
        float accN = __shfl_down_sync(0xFFFFFFFFu, acc, 1);
        if ((t & 1) == 0) {
            int c = cbase + t;
            int head = c >> 6;
            int p = (c & 63) >> 1;
            __nv_bfloat162 pk = __floats2bfloat162_rn(acc, accN);
            g_hb16[g * 128 + p * 4 + head] = *(unsigned int*)&pk;
        }
        if (half == 0 && t < 64) {
            float l = linb[t];
            for (int k = 0; k < 65; k++) l += sx[k] * linW[k * 64 + t];
            g_lin1[g * 64 + t] = l;
        }
        if (t < 2) {
            int h = half * 2 + t;
            float s = 0.f, d = 0.f;
            for (int k = 0; k < 65; k++) {
                s += sx[k] * sES[k * 2 + t];
                d += sx[k] * sED[k * 2 + t];
            }
            g_es1[g * 4 + h] = s;
            g_ed1[g * 4 + h] = d;
        }
        __syncthreads();
    }
}

// ---------------- K3: GAT1 aggregation (warp/node, chunked smem alphas, no max pass) ----
__global__ __launch_bounds__(256) void k3(const float* __restrict__ conv1_b) {
    __shared__ float4 sw[8][32];
    __shared__ int ssrc[8][32];
    int wi = threadIdx.x >> 5;
    int lane = threadIdx.x & 31;
    int g = blockIdx.x * 8 + wi;
    if (g >= G) return;
    int o = g_off[g];
    int deg = g_off[g + 1] - o;
    float4 ed = *(const float4*)&g_ed1[g * 4];

    float2 a0 = {0.f, 0.f}, a1 = {0.f, 0.f}, a2 = {0.f, 0.f}, a3 = {0.f, 0.f};
    float d0 = 0.f, d1 = 0.f, d2 = 0.f, d3 = 0.f;

    for (int base = -1; base < deg; base += 32) {
        int e = base + lane;
        float4 xv = {0.f, 0.f, 0.f, 0.f};
        int s = 0;
        if (e < deg) {
            s = (e < 0) ? g : g_csr[o + e];
            float4 es = *(const float4*)&g_es1[s * 4];
            xv.x = eexp(lrelu(es.x + ed.x));
            xv.y = eexp(lrelu(es.y + ed.y));
            xv.z = eexp(lrelu(es.z + ed.z));
            xv.w = eexp(lrelu(es.w + ed.w));
            d0 += xv.x; d1 += xv.y; d2 += xv.z; d3 += xv.w;
        }
        sw[wi][lane] = xv;
        ssrc[wi][lane] = s;
        __syncwarp();
        int n = min(32, deg - base);
#pragma unroll 4
        for (int i = 0; i < n; i++) {
            int s2 = ssrc[wi][i];
            float4 w4 = sw[wi][i];
            uint4 hv = *(const uint4*)&g_hb16[s2 * 128 + lane * 4];
            float2 v0 = __bfloat1622float2(*reinterpret_cast<const __nv_bfloat162*>(&hv.x));
            float2 v1 = __bfloat1622float2(*reinterpret_cast<const __nv_bfloat162*>(&hv.y));
            float2 v2 = __bfloat1622float2(*reinterpret_cast<const __nv_bfloat162*>(&hv.z));
            float2 v3 = __bfloat1622float2(*reinterpret_cast<const __nv_bfloat162*>(&hv.w));
            a0.x += w4.x * v0.x; a0.y += w4.x * v0.y;
            a1.x += w4.y * v1.x; a1.y += w4.y * v1.y;
            a2.x += w4.z * v2.x; a2.y += w4.z * v2.y;
            a3.x += w4.w * v3.x; a3.y += w4.w * v3.y;
        }
        __syncwarp();
    }
    d0 = wredsum(d0); d1 = wredsum(d1); d2 = wredsum(d2); d3 = wredsum(d3);
    float i0 = 1.f / d0, i1 = 1.f / d1, i2 = 1.f / d2, i3 = 1.f / d3;
    int c0 = lane * 2;
    float o0 = 0.25f * (a0.x * i0 + a1.x * i1 + a2.x * i2 + a3.x * i3)
             + conv1_b[c0] + g_lin1[g * 64 + c0];
    float o1 = 0.25f * (a0.y * i0 + a1.y * i1 + a2.y * i2 + a3.y * i3)
             + conv1_b[c0 + 1] + g_lin1[g * 64 + c0 + 1];
    float2 r;
    r.x = sigmoidf(o0);
    r.y = sigmoidf(o1);
    *(float2*)&g_h1[g * 64 + c0] = r;
}

// ---------------- K4: layer-2 per-node projections -> packed {es2,h2h} ----------------
__global__ __launch_bounds__(256) void k4(const float* __restrict__ c2W, const float* __restrict__ c2as,
                                          const float* __restrict__ c2ad, const float* __restrict__ l2W) {
    int warp = (blockIdx.x * blockDim.x + threadIdx.x) >> 5;
    if (warp >= G) return;
    int lane = threadIdx.x & 31;
    int g = warp;
    int c0 = lane * 2;
    float2 hv = *(const float2*)&g_h1[g * 64 + c0];
    float d0 = hv.x * c2W[c0 * 4 + 0] + hv.y * c2W[(c0 + 1) * 4 + 0];
    float d1 = hv.x * c2W[c0 * 4 + 1] + hv.y * c2W[(c0 + 1) * 4 + 1];
    float d2 = hv.x * c2W[c0 * 4 + 2] + hv.y * c2W[(c0 + 1) * 4 + 2];
    float d3 = hv.x * c2W[c0 * 4 + 3] + hv.y * c2W[(c0 + 1) * 4 + 3];
    float d4 = hv.x * l2W[c0] + hv.y * l2W[c0 + 1];
    d0 = wredsum(d0); d1 = wredsum(d1); d2 = wredsum(d2); d3 = wredsum(d3); d4 = wredsum(d4);
    if (lane == 0) {
        float4 es = {d0 * c2as[0], d1 * c2as[1], d2 * c2as[2], d3 * c2as[3]};
        float4 hh = {d0, d1, d2, d3};
        *(float4*)&g_pack2[g * 8] = es;
        *(float4*)&g_pack2[g * 8 + 4] = hh;
        float4 edv = {d0 * c2ad[0], d1 * c2ad[1], d2 * c2ad[2], d3 * c2ad[3]};
        *(float4*)&g_ed2[g * 4] = edv;
        g_lin2[g] = d4;
    }
}

// ---------------- K5: GAT2 aggregation (single pass, no max) ----------------
__global__ __launch_bounds__(256) void k5(const float* __restrict__ c2b, const float* __restrict__ l2b) {
    int warp = (blockIdx.x * blockDim.x + threadIdx.x) >> 5;
    if (warp >= G) return;
    int lane = threadIdx.x & 31;
    int g = warp;
    int o = g_off[g];
    int deg = g_off[g + 1] - o;
    float4 ed = *(const float4*)&g_ed2[g * 4];
    float de0 = 0.f, de1 = 0.f, de2 = 0.f, de3 = 0.f;
    float a0 = 0.f, a1 = 0.f, a2 = 0.f, a3 = 0.f;
    for (int e = lane - 1; e < deg; e += 32) {
        int s = (e < 0) ? g : g_csr[o + e];
        float4 es = *(const float4*)&g_pack2[s * 8];
        float4 h2 = *(const float4*)&g_pack2[s * 8 + 4];
        float x0 = eexp(lrelu(es.x + ed.x));
        float x1 = eexp(lrelu(es.y + ed.y));
        float x2 = eexp(lrelu(es.z + ed.z));
        float x3 = eexp(lrelu(es.w + ed.w));
        de0 += x0; de1 += x1; de2 += x2; de3 += x3;
        a0 += x0 * h2.x; a1 += x1 * h2.y; a2 += x2 * h2.z; a3 += x3 * h2.w;
    }
    de0 = wredsum(de0); de1 = wredsum(de1); de2 = wredsum(de2); de3 = wredsum(de3);
    a0 = wredsum(a0); a1 = wredsum(a1); a2 = wredsum(a2); a3 = wredsum(a3);
    if (lane == 0) {
        float r = 0.25f * (a0 / de0 + a1 / de1 + a2 / de2 + a3 / de3);
        g_feat[g] = sigmoidf(r + c2b[0] + g_lin2[g] + l2b[0]);
    }
}

// ---------------- K6: pert MLP ----------------
__global__ __launch_bounds__(128) void k6(const float* __restrict__ pert, const float* __restrict__ W1,
                                          const float* __restrict__ b1, const float* __restrict__ W2,
                                          const float* __restrict__ b2) {
    __shared__ float sp[PDIM];
    __shared__ float s1[128];
    int b = blockIdx.x, t = threadIdx.x;
    for (int i = t; i < PDIM; i += 128) sp[i] = pert[b * PDIM + i];
    __syncthreads();
    float a = b1[t];
    for (int k = 0; k < PDIM; k++) a += sp[k] * W1[k * 128 + t];
    s1[t] = sigmoidf(a);
    __syncthreads();
    if (t < 64) {
        float o = b2[t];
        for (int k = 0; k < 128; k++) o += s1[k] * W2[k * 64 + t];
        g_pout[b * 64 + t] = o;
    }
}

// ---------------- GEMM1 (tensor cores, bf16 split): partials to g_part1 ----------------
__global__ __launch_bounds__(256, 2) void gemm1_tc(const float* __restrict__ ctrl,
                                                   const float* __restrict__ W1) {
    using namespace nvcuda;
    __shared__ __align__(16) __nv_bfloat16 sAh[128 * 48], sAl[128 * 48];
    __shared__ __align__(16) __nv_bfloat16 sBh[32 * 72], sBl[32 * 72];
    int t = threadIdx.x;
    int n0 = blockIdx.x * 64;
    int sk = blockIdx.y;
    int cb = (sk * 625) >> 4, ce = ((sk + 1) * 625) >> 4;
    int warp = t >> 5, wm = warp & 3, wn = warp >> 2;

    wmma::fragment<wmma::accumulator, 16, 16, 16, float> acc[2][2];
#pragma unroll
    for (int mi = 0; mi < 2; mi++)
#pragma unroll
        for (int ni = 0; ni < 2; ni++) wmma::fill_fragment(acc[mi][ni], 0.f);

    float4 ra[4];
    float4 rb[2];

    auto loadAB = [&](int kk) {
#pragma unroll
        for (int i = 0; i < 4; i++) {
            int lin = t + i * 256;
            int b = lin >> 3, kq = lin & 7;
            int k = kk + kq * 4;
            float4 c4 = *(const float4*)&ctrl[b * G + k];
            float4 f4 = *(const float4*)&g_feat[k];
            ra[i].x = c4.x + f4.x; ra[i].y = c4.y + f4.y;
            ra[i].z = c4.z + f4.z; ra[i].w = c4.w + f4.w;
        }
#pragma unroll
        for (int i = 0; i < 2; i++) {
            int lin = t + i * 256;
            int r = lin >> 4, cq = lin & 15;
            rb[i] = *(const float4*)&W1[(kk + r) * 1024 + n0 + cq * 4];
        }
    };
    auto storeAB = [&]() {
#pragma unroll
        for (int i = 0; i < 4; i++) {
            int lin = t + i * 256;
            int b = lin >> 3, kq = lin & 7;
            const float* v = (const float*)&ra[i];
#pragma unroll
            for (int j = 0; j < 4; j++) {
                __nv_bfloat16 h, l;
                split2(v[j], h, l);
                sAh[b * 48 + kq * 4 + j] = h;
                sAl[b * 48 + kq * 4 + j] = l;
            }
        }
#pragma unroll
        for (int i = 0; i < 2; i++) {
            int lin = t + i * 256;
            int r = lin >> 4, cq = lin & 15;
            const float* v = (const float*)&rb[i];
#pragma unroll
            for (int j = 0; j < 4; j++) {
                __nv_bfloat16 h, l;
                split2(v[j], h, l);
                sBh[r * 72 + cq * 4 + j] = h;
                sBl[r * 72 + cq * 4 + j] = l;
            }
        }
    };

    loadAB(cb * 32);
    for (int c = cb; c < ce; c++) {
        storeAB();
        __syncthreads();
        if (c + 1 < ce) loadAB((c + 1) * 32);
#pragma unroll
        for (int ks = 0; ks < 2; ks++) {
            wmma::fragment<wmma::matrix_a, 16, 16, 16, __nv_bfloat16, wmma::row_major> ah[2], al[2];
            wmma::fragment<wmma::matrix_b, 16, 16, 16, __nv_bfloat16, wmma::row_major> bh[2], bl[2];
#pragma unroll
            for (int mi = 0; mi < 2; mi++) {
                wmma::load_matrix_sync(ah[mi], &sAh[(wm * 32 + mi * 16) * 48 + ks * 16], 48);
                wmma::load_matrix_sync(al[mi], &sAl[(wm * 32 + mi * 16) * 48 + ks * 16], 48);
            }
#pragma unroll
            for (int ni = 0; ni < 2; ni++) {
                wmma::load_matrix_sync(bh[ni], &sBh[(ks * 16) * 72 + wn * 32 + ni * 16], 72);
                wmma::load_matrix_sync(bl[ni], &sBl[(ks * 16) * 72 + wn * 32 + ni * 16], 72);
            }
#pragma unroll
            for (int mi = 0; mi < 2; mi++)
#pragma unroll
                for (int ni = 0; ni < 2; ni++) {
                    wmma::mma_sync(acc[mi][ni], ah[mi], bh[ni], acc[mi][ni]);
                    wmma::mma_sync(acc[mi][ni], ah[mi], bl[ni], acc[mi][ni]);
                    wmma::mma_sync(acc[mi][ni], al[mi], bh[ni], acc[mi][ni]);
                }
        }
        __syncthreads();
    }
    float* pout = g_part1 + sk * (NB * 1024);
#pragma unroll
    for (int mi = 0; mi < 2; mi++)
#pragma unroll
        for (int ni = 0; ni < 2; ni++)
            wmma::store_matrix_sync(&pout[(wm * 32 + mi * 16) * 1024 + n0 + wn * 32 + ni * 16],
                                    acc[mi][ni], 1024, wmma::mem_row_major);
}

// ---------------- K8: reduce partials + pert columns + bias + sigmoid -> bf16 hid ------
__global__ __launch_bounds__(256) void k8(const float* __restrict__ W1, const float* __restrict__ b1) {
    __shared__ float sp[16 * 64];
    int t = threadIdx.x;
    int j = blockIdx.x * 256 + t;
    int b0 = blockIdx.y * 16;
    for (int i = t; i < 16 * 64; i += 256) sp[i] = g_pout[(b0 + (i >> 6)) * 64 + (i & 63)];
    float w[64];
#pragma unroll
    for (int k = 0; k < 64; k++) w[k] = W1[(G + k) * 1024 + j];
    __syncthreads();
    float bj = b1[j];
    for (int bi = 0; bi < 16; bi++) {
        int b = b0 + bi;
        float s = bj;
#pragma unroll
        for (int p = 0; p < 16; p++) s += g_part1[p * (NB * 1024) + b * 1024 + j];
#pragma unroll
        for (int k = 0; k < 64; k++) s += sp[bi * 64 + k] * w[k];
        float v = sigmoidf(s);
        __nv_bfloat16 h, l;
        split2(v, h, l);
        g_hid_hi[b * 1024 + j] = h;
        g_hid_lo[b * 1024 + j] = l;
    }
}

// ---------------- GEMM2 (tensor cores): out = hid[128,1024] @ W2[1024,20000] + b2 ------
__global__ __launch_bounds__(256, 2) void gemm2_tc(const float* __restrict__ Bw,
                                                   const float* __restrict__ bias,
                                                   float* __restrict__ Co) {
    using namespace nvcuda;
    __shared__ __align__(16) char pool[128 * 72 * 4];
    __nv_bfloat16* sAh = (__nv_bfloat16*)pool;
    __nv_bfloat16* sAl = sAh + 128 * 48;
    __nv_bfloat16* sBh = (__nv_bfloat16*)(pool + 24576);
    __nv_bfloat16* sBl = sBh + 32 * 72;
    float* sOut = (float*)pool;

    int t = threadIdx.x;
    int n0 = blockIdx.x * 64;
    int warp = t >> 5, wm = warp & 3, wn = warp >> 2;

    wmma::fragment<wmma::accumulator, 16, 16, 16, float> acc[2][2];
#pragma unroll
    for (int mi = 0; mi < 2; mi++)
#pragma unroll
        for (int ni = 0; ni < 2; ni++) wmma::fill_fragment(acc[mi][ni], 0.f);

    uint4 rah[2], ral[2];
    float4 rb[2];

    auto loadAB = [&](int kk) {
#pragma unroll
        for (int i = 0; i < 2; i++) {
            int lin = t + i * 256;
            int b = lin >> 2, kq = lin & 3;
            int k = kk + kq * 8;
            rah[i] = *(const uint4*)&g_hid_hi[b * 1024 + k];
            ral[i] = *(const uint4*)&g_hid_lo[b * 1024 + k];
        }
#pragma unroll
        for (int i = 0; i < 2; i++) {
            int lin = t + i * 256;
            int r = lin >> 4, cq = lin & 15;
            int col = n0 + cq * 4;
            if (col < G) rb[i] = *(const float4*)&Bw[(kk + r) * G + col];
            else { rb[i].x = rb[i].y = rb[i].z = rb[i].w = 0.f; }
        }
    };
    auto storeAB = [&]() {
#pragma unroll
        for (int i = 0; i < 2; i++) {
            int lin = t + i * 256;
            int b = lin >> 2, kq = lin & 3;
            *(uint4*)&sAh[b * 48 + kq * 8] = rah[i];
            *(uint4*)&sAl[b * 48 + kq * 8] = ral[i];
        }
#pragma unroll
        for (int i = 0; i < 2; i++) {
            int lin = t + i * 256;
            int r = lin >> 4, cq = lin & 15;
            const float* v = (const float*)&rb[i];
#pragma unroll
            for (int j = 0; j < 4; j++) {
                __nv_bfloat16 h, l;
                split2(v[j], h, l);
                sBh[r * 72 + cq * 4 + j] = h;
                sBl[r * 72 + cq * 4 + j] = l;
            }
        }
    };

    loadAB(0);
    for (int c = 0; c < 32; c++) {
        storeAB();
        __syncthreads();
        if (c + 1 < 32) loadAB((c + 1) * 32);
#pragma unroll
        for (int ks = 0; ks < 2; ks++) {
            wmma::fragment<wmma::matrix_a, 16, 16, 16, __nv_bfloat16, wmma::row_major> ah[2], al[2];
            wmma::fragment<wmma::matrix_b, 16, 16, 16, __nv_bfloat16, wmma::row_major> bh[2], bl[2];
#pragma unroll
            for (int mi = 0; mi < 2; mi++) {
                wmma::load_matrix_sync(ah[mi], &sAh[(wm * 32 + mi * 16) * 48 + ks * 16], 48);
                wmma::load_matrix_sync(al[mi], &sAl[(wm * 32 + mi * 16) * 48 + ks * 16], 48);
            }
#pragma unroll
            for (int ni = 0; ni < 2; ni++) {
                wmma::load_matrix_sync(bh[ni], &sBh[(ks * 16) * 72 + wn * 32 + ni * 16], 72);
                wmma::load_matrix_sync(bl[ni], &sBl[(ks * 16) * 72 + wn * 32 + ni * 16], 72);
            }
#pragma unroll
            for (int mi = 0; mi < 2; mi++)
#pragma unroll
                for (int ni = 0; ni < 2; ni++) {
                    wmma::mma_sync(acc[mi][ni], ah[mi], bh[ni], acc[mi][ni]);
                    wmma::mma_sync(acc[mi][ni], ah[mi], bl[ni], acc[mi][ni]);
                    wmma::mma_sync(acc[mi][ni], al[mi], bh[ni], acc[mi][ni]);
                }
        }
        __syncthreads();
    }

#pragma unroll
    for (int mi = 0; mi < 2; mi++)
#pragma unroll
        for (int ni = 0; ni < 2; ni++)
            wmma::store_matrix_sync(&sOut[(wm * 32 + mi * 16) * 72 + wn * 32 + ni * 16],
                                    acc[mi][ni], 72, wmma::mem_row_major);
    __syncthreads();
#pragma unroll
    for (int i = 0; i < 8; i++) {
        int lin = t + i * 256;
        int row = lin >> 4;
        int c4 = (lin & 15) * 4;
        int col = n0 + c4;
        if (col < G) {
            float4 v = *(const float4*)&sOut[row * 72 + c4];
            float4 bb = *(const float4*)&bias[col];
            v.x += bb.x; v.y += bb.y; v.z += bb.z; v.w += bb.w;
            *(float4*)&Co[row * G + col] = v;
        }
    }
}

// ---------------- launch ----------------
extern "C" void kernel_launch(void* const* d_in, const int* in_sizes, int n_in,
                              void* d_out, int out_size) {
    const float* x = (const float*)d_in[0];
    const int* ei = (const int*)d_in[1];
    const int* pos = (const int*)d_in[2];
    const float* ctrl = (const float*)d_in[3];
    const float* pert = (const float*)d_in[4];
    const float* ge = (const float*)d_in[5];
    const float* c1W = (const float*)d_in[6];
    const float* c1as = (const float*)d_in[7];
    const float* c1ad = (const float*)d_in[8];
    const float* c1b = (const float*)d_in[9];
    const float* l1W = (const float*)d_in[10];
    const float* l1b = (const float*)d_in[11];
    const float* c2W = (const float*)d_in[12];
    const float* c2as = (const float*)d_in[13];
    const float* c2ad = (const float*)d_in[14];
    const float* c2b = (const float*)d_in[15];
    const float* l2W = (const float*)d_in[16];
    const float* l2b = (const float*)d_in[17];
    const float* pW1 = (const float*)d_in[18];
    const float* pb1 = (const float*)d_in[19];
    const float* pW2 = (const float*)d_in[20];
    const float* pb2 = (const float*)d_in[21];
    const float* prW1 = (const float*)d_in[22];
    const float* prb1 = (const float*)d_in[23];
    const float* prW2 = (const float*)d_in[24];
    const float* prb2 = (const float*)d_in[25];
    float* out = (float*)d_out;

    k_zero_deg<<<(G + 255) / 256, 256>>>();
    k_hist<<<(NE / 4 + 255) / 256, 256>>>(ei);
    k_scan<<<1, 1024>>>();
    k_scatter<<<(NE / 4 + 255) / 256, 256>>>(ei);
    k1<<<dim3(1000, 2), 128>>>(x, pos, ge, c1W, c1as, c1ad, l1W, l1b);
    k3<<<(G + 7) / 8, 256>>>(c1b);
    k4<<<(G * 32 + 255) / 256, 256>>>(c2W, c2as, c2ad, l2W);
    k5<<<(G * 32 + 255) / 256, 256>>>(c2b, l2b);
    k6<<<NB, 128>>>(pert, pW1, pb1, pW2, pb2);
    gemm1_tc<<<dim3(16, 16), 256>>>(ctrl, prW1);
    k8<<<dim3(4, 8), 256>>>(prW1, prb1);
    gemm2_tc<<<313, 256>>>(prW2, prb2, out);
}